// round 16
// baseline (speedup 1.0000x reference)
#include <cuda_runtime.h>
#include <cuda_bf16.h>

#define NN 100000
#define FF 64
#define HH 8
#define DD 8
#define EE 1200000
#define HID 32

// scratch (allocation-free rule: __device__ globals)
__device__ float g_src_buf[NN * FF];
__device__ float g_dst_buf[NN * FF];
__device__ int g_idx_is64;

__device__ __forceinline__ float leaky(float x) { return fmaxf(x, 0.2f * x); }
__device__ __forceinline__ float sigm(float x) { return 1.0f / (1.0f + __expf(-x)); }

__device__ __forceinline__ void red4(float* p, float x, float y, float z, float w) {
    asm volatile("red.global.add.v4.f32 [%0], {%1,%2,%3,%4};"
                 :: "l"(p), "f"(x), "f"(y), "f"(z), "f"(w) : "memory");
}

__device__ __forceinline__ unsigned pack_bf16(float lo, float hi) {
    __nv_bfloat162 t = __float22bfloat162_rn(make_float2(lo, hi));
    return *(unsigned*)&t;
}

// split x into bf16 hi + bf16 lo (residual)
__device__ __forceinline__ void split_pack(float a, float b, unsigned& hi, unsigned& lo) {
    __nv_bfloat16 ah = __float2bfloat16(a), bh = __float2bfloat16(b);
    float ar = a - __bfloat162float(ah);
    float br = b - __bfloat162float(bh);
    __nv_bfloat162 t; t.x = ah; t.y = bh;
    hi = *(unsigned*)&t;
    lo = pack_bf16(ar, br);
}

// D += A@B, m16n8k16, bf16 in / fp32 accum
__device__ __forceinline__ void mma16816(float* d, const unsigned* a, const unsigned* b) {
    asm volatile(
        "mma.sync.aligned.m16n8k16.row.col.f32.bf16.bf16.f32 "
        "{%0,%1,%2,%3}, {%4,%5,%6,%7}, {%8,%9}, {%0,%1,%2,%3};"
        : "+f"(d[0]), "+f"(d[1]), "+f"(d[2]), "+f"(d[3])
        : "r"(a[0]), "r"(a[1]), "r"(a[2]), "r"(a[3]), "r"(b[0]), "r"(b[1]));
}

#define LMW32 36               // staging row stride in uint32 (72 bf16), conflict-free
#define ATTS 10                // att row stride (node kernel only)

// ---------------------------------------------------------------------------
// Fused node kernel (unchanged): tensor-core GEMM (hi/lo split) + node att.
__global__ __launch_bounds__(128) void node_kernel(
    const float* __restrict__ h,
    const float* __restrict__ W_src, const float* __restrict__ b_src,
    const float* __restrict__ W_dst, const float* __restrict__ b_dst,
    const float* __restrict__ Wa1, const float* __restrict__ ba1,
    const float* __restrict__ Wa2, const float* __restrict__ ba2,
    const unsigned int* __restrict__ eidx_words,
    float* __restrict__ out)
{
    __shared__ unsigned AHI[128 * LMW32];
    __shared__ unsigned ALO[128 * LMW32];
    __shared__ float ATT[4][32 * ATTS];

    const int tid  = threadIdx.x;
    const int warp = tid >> 5;
    const int lane = tid & 31;
    const int c = lane & 3;
    const int r = lane >> 2;
    const int blockbase = blockIdx.x * 128;

    if (blockIdx.x == 0 && tid == 0) {
        int is64 = 1;
        for (int i = 0; i < 8; i++)
            if (eidx_words[2 * i + 1] != 0u) is64 = 0;
        g_idx_is64 = is64;
    }

    const int mat = warp >> 1;
    const int colbase = 32 * (warp & 1);
    const float* Wm = mat ? W_dst : W_src;
    const float* bm = mat ? b_dst : b_src;

    unsigned bhi[4][4][2], blo[4][4][2];
    #pragma unroll
    for (int ks = 0; ks < 4; ks++)
        #pragma unroll
        for (int nt = 0; nt < 4; nt++) {
            const float* base = Wm + (16 * ks + 2 * c) * FF + colbase + 8 * nt + r;
            split_pack(base[0],       base[FF],     bhi[ks][nt][0], blo[ks][nt][0]);
            split_pack(base[8 * FF],  base[9 * FF], bhi[ks][nt][1], blo[ks][nt][1]);
        }
    float gb0[4], gb1[4];
    #pragma unroll
    for (int nt = 0; nt < 4; nt++) {
        gb0[nt] = bm[colbase + 8 * nt + 2 * c];
        gb1[nt] = bm[colbase + 8 * nt + 2 * c + 1];
    }

    unsigned w1f[4][4][2];
    #pragma unroll
    for (int ks = 0; ks < 4; ks++)
        #pragma unroll
        for (int nt = 0; nt < 4; nt++) {
            const float* base = Wa1 + (16 * ks + 2 * c) * HID + 8 * nt + r;
            w1f[ks][nt][0] = pack_bf16(base[0],        base[HID]);
            w1f[ks][nt][1] = pack_bf16(base[8 * HID],  base[9 * HID]);
        }
    unsigned w2f[2][2];
    #pragma unroll
    for (int ks = 0; ks < 2; ks++) {
        const float* base = Wa2 + (16 * ks + 2 * c) * HH + r;
        w2f[ks][0] = pack_bf16(base[0],      base[HH]);
        w2f[ks][1] = pack_bf16(base[8 * HH], base[9 * HH]);
    }
    float bb0[4], bb1[4];
    #pragma unroll
    for (int nt = 0; nt < 4; nt++) {
        bb0[nt] = ba1[8 * nt + 2 * c];
        bb1[nt] = ba1[8 * nt + 2 * c + 1];
    }
    const float b2r0 = ba2[2 * c], b2r1 = ba2[2 * c + 1];

    #pragma unroll
    for (int e = 0; e < 32; e++) {
        int row = blockbase + 32 * warp + e;
        float2 v = (row < NN) ? *(const float2*)(h + (size_t)row * FF + 2 * lane)
                              : make_float2(0.0f, 0.0f);
        unsigned hv, lv;
        split_pack(v.x, v.y, hv, lv);
        AHI[(32 * warp + e) * LMW32 + lane] = hv;
        ALO[(32 * warp + e) * LMW32 + lane] = lv;
    }
    __syncthreads();

    float* gout = mat ? g_dst_buf : g_src_buf;
    #pragma unroll
    for (int mt = 0; mt < 8; mt++) {
        float acc[4][4];
        #pragma unroll
        for (int nt = 0; nt < 4; nt++)
            acc[nt][0] = acc[nt][1] = acc[nt][2] = acc[nt][3] = 0.0f;

        #pragma unroll
        for (int ks = 0; ks < 4; ks++) {
            int base = (mt * 16 + r) * LMW32 + 8 * ks + c;
            unsigned ah[4], al[4];
            ah[0] = AHI[base];                 al[0] = ALO[base];
            ah[1] = AHI[base + 8 * LMW32];     al[1] = ALO[base + 8 * LMW32];
            ah[2] = AHI[base + 4];             al[2] = ALO[base + 4];
            ah[3] = AHI[base + 8 * LMW32 + 4]; al[3] = ALO[base + 8 * LMW32 + 4];
            #pragma unroll
            for (int nt = 0; nt < 4; nt++) {
                mma16816(acc[nt], ah, blo[ks][nt]);
                mma16816(acc[nt], al, bhi[ks][nt]);
                mma16816(acc[nt], ah, bhi[ks][nt]);
            }
        }

        int row0 = blockbase + 16 * mt + r;
        int row8 = row0 + 8;
        #pragma unroll
        for (int nt = 0; nt < 4; nt++) {
            int col = colbase + 8 * nt + 2 * c;
            if (row0 < NN)
                *(float2*)(gout + (size_t)row0 * FF + col) =
                    make_float2(acc[nt][0] + gb0[nt], acc[nt][1] + gb1[nt]);
            if (row8 < NN)
                *(float2*)(gout + (size_t)row8 * FF + col) =
                    make_float2(acc[nt][2] + gb0[nt], acc[nt][3] + gb1[nt]);
        }
    }
    __syncthreads();

    const int nbase = blockbase + 32 * warp;
    if (nbase >= NN) return;

    unsigned* lmW = &AHI[(32 * warp) * LMW32];
    float* attW = &ATT[warp][0];
    const int myh = lane >> 2;

    #pragma unroll
    for (int e = 0; e < 32; e++) {
        float2 dv = *(const float2*)(g_dst_buf + (size_t)(nbase + e) * FF + 2 * lane);
        lmW[e * LMW32 + lane] = pack_bf16(leaky(dv.x), leaky(dv.y));
    }
    __syncwarp();

    #pragma unroll
    for (int mt = 0; mt < 2; mt++) {
        float acc[4][4];
        #pragma unroll
        for (int nt = 0; nt < 4; nt++)
            acc[nt][0] = acc[nt][1] = acc[nt][2] = acc[nt][3] = 0.0f;

        #pragma unroll
        for (int ks = 0; ks < 4; ks++) {
            unsigned a[4];
            int base = (mt * 16 + r) * LMW32 + 8 * ks + c;
            a[0] = lmW[base];
            a[1] = lmW[base + 8 * LMW32];
            a[2] = lmW[base + 4];
            a[3] = lmW[base + 8 * LMW32 + 4];
            #pragma unroll
            for (int nt = 0; nt < 4; nt++)
                mma16816(acc[nt], a, w1f[ks][nt]);
        }

        unsigned a2[2][4];
        #pragma unroll
        for (int nt = 0; nt < 4; nt++) {
            float v0 = leaky(acc[nt][0] + bb0[nt]);
            float v1 = leaky(acc[nt][1] + bb1[nt]);
            float v2 = leaky(acc[nt][2] + bb0[nt]);
            float v3 = leaky(acc[nt][3] + bb1[nt]);
            a2[nt >> 1][(nt & 1) * 2 + 0] = pack_bf16(v0, v1);
            a2[nt >> 1][(nt & 1) * 2 + 1] = pack_bf16(v2, v3);
        }

        float z[4] = {0.0f, 0.0f, 0.0f, 0.0f};
        mma16816(z, a2[0], w2f[0]);
        mma16816(z, a2[1], w2f[1]);

        *(float2*)&attW[(mt * 16 + r) * ATTS + 2 * c] =
            make_float2(sigm(z[0] + b2r0), sigm(z[1] + b2r1));
        *(float2*)&attW[(mt * 16 + r + 8) * ATTS + 2 * c] =
            make_float2(sigm(z[2] + b2r0), sigm(z[3] + b2r1));
    }
    __syncwarp();

    #pragma unroll
    for (int e = 0; e < 32; e++) {
        float av = attW[e * ATTS + myh];
        float2 dv = *(const float2*)(g_dst_buf + (size_t)(nbase + e) * FF + 2 * lane);
        *(float2*)(out + (size_t)(nbase + e) * FF + 2 * lane) =
            make_float2(av * dv.x, av * dv.y);
    }
}

// ---------------------------------------------------------------------------
// Edge kernel v9: v8 (reg-att + shfl exchange, gather-before-MMA, one
// syncwarp after scatter) + ALL edge indices preloaded into shared at start.
// Index access = broadcast LDS.64 instead of 2x SHFL; no index shfls remain.
__global__ __launch_bounds__(128, 5) void edge_kernel(
    const void* __restrict__ edge_index,
    const float* __restrict__ Wa1, const float* __restrict__ ba1,
    const float* __restrict__ Wa2, const float* __restrict__ ba2,
    float* __restrict__ out)
{
    __shared__ unsigned LM[4][2][32 * LMW32];   // double-buffered per warp
    __shared__ int2 EIDX[4][5 * 32];            // (src,dst) per edge, per warp

    const int tid  = threadIdx.x;
    const int warp = tid >> 5;
    const int lane = tid & 31;
    const int c = lane & 3;
    const int r = lane >> 2;
    const int half = lane >> 4;      // which edge of the pair
    const int sub  = lane & 15;      // 16B chunk within row
    const int hsel = (sub >> 1) & 1; // which of the source lane's 2 heads
    const int hquad = sub >> 2;      // source-lane column (head/2)

    unsigned w1f[4][4][2];
    #pragma unroll
    for (int ks = 0; ks < 4; ks++)
        #pragma unroll
        for (int nt = 0; nt < 4; nt++) {
            const float* base = Wa1 + (16 * ks + 2 * c) * HID + 8 * nt + r;
            w1f[ks][nt][0] = pack_bf16(base[0],        base[HID]);
            w1f[ks][nt][1] = pack_bf16(base[8 * HID],  base[9 * HID]);
        }
    unsigned w2f[2][2];
    #pragma unroll
    for (int ks = 0; ks < 2; ks++) {
        const float* base = Wa2 + (16 * ks + 2 * c) * HH + r;
        w2f[ks][0] = pack_bf16(base[0],      base[HH]);
        w2f[ks][1] = pack_bf16(base[8 * HH], base[9 * HH]);
    }
    float bb0[4], bb1[4];
    #pragma unroll
    for (int nt = 0; nt < 4; nt++) {
        bb0[nt] = ba1[8 * nt + 2 * c];
        bb1[nt] = ba1[8 * nt + 2 * c + 1];
    }
    const float b2r0 = ba2[2 * c], b2r1 = ba2[2 * c + 1];

    const int wbase = (blockIdx.x * 4 + warp) * 5;

    // ---- preload all 5 batches' indices into shared (coalesced) ----
    {
        const int is64 = g_idx_is64;
        #pragma unroll
        for (int b = 0; b < 5; b++) {
            const int ebase = (wbase + b) * 32;
            int s, d;
            if (is64) {
                const long long* ei = (const long long*)edge_index;
                s = (int)ei[ebase + lane];
                d = (int)ei[EE + ebase + lane];
            } else {
                const int* ei = (const int*)edge_index;
                s = ei[ebase + lane];
                d = ei[EE + ebase + lane];
            }
            EIDX[warp][b * 32 + lane] = make_int2(s, d);
        }
    }
    __syncwarp();

    const int2* eW = &EIDX[warp][0];

    // gather a full batch (fp32 rows) into LM buffer; indices via bcast LDS
    auto gather = [&](int b, unsigned* lmB) {
        #pragma unroll
        for (int i = 0; i < 16; i++) {
            int e = 2 * i + half;
            int2 sd = eW[b * 32 + e];
            float4 sv = *(const float4*)(g_src_buf + (size_t)sd.x * FF + 4 * sub);
            float4 dv = *(const float4*)(g_dst_buf + (size_t)sd.y * FF + 4 * sub);
            *(uint2*)&lmB[e * LMW32 + 2 * sub] = make_uint2(
                pack_bf16(leaky(sv.x + dv.x), leaky(sv.y + dv.y)),
                pack_bf16(leaky(sv.z + dv.z), leaky(sv.w + dv.w)));
        }
    };

    gather(0, &LM[warp][0][0]);
    __syncwarp();

    for (int b = 0; b < 5; b++) {
        // issue next batch's gather (other buffer, no sync — hides under MMA)
        if (b < 4) gather(b + 1, &LM[warp][(b + 1) & 1][0]);

        // ---- MMA MLP on batch b (att kept in registers, sigm applied) ----
        unsigned* lmW = &LM[warp][b & 1][0];
        float za[2][4];
        #pragma unroll
        for (int mt = 0; mt < 2; mt++) {
            float acc[4][4];
            #pragma unroll
            for (int nt = 0; nt < 4; nt++)
                acc[nt][0] = acc[nt][1] = acc[nt][2] = acc[nt][3] = 0.0f;

            #pragma unroll
            for (int ks = 0; ks < 4; ks++) {
                unsigned a[4];
                int base = (mt * 16 + r) * LMW32 + 8 * ks + c;
                a[0] = lmW[base];
                a[1] = lmW[base + 8 * LMW32];
                a[2] = lmW[base + 4];
                a[3] = lmW[base + 8 * LMW32 + 4];
                #pragma unroll
                for (int nt = 0; nt < 4; nt++)
                    mma16816(acc[nt], a, w1f[ks][nt]);
            }

            unsigned a2[2][4];
            #pragma unroll
            for (int nt = 0; nt < 4; nt++) {
                float v0 = leaky(acc[nt][0] + bb0[nt]);
                float v1 = leaky(acc[nt][1] + bb1[nt]);
                float v2 = leaky(acc[nt][2] + bb0[nt]);
                float v3 = leaky(acc[nt][3] + bb1[nt]);
                a2[nt >> 1][(nt & 1) * 2 + 0] = pack_bf16(v0, v1);
                a2[nt >> 1][(nt & 1) * 2 + 1] = pack_bf16(v2, v3);
            }

            float z[4] = {0.0f, 0.0f, 0.0f, 0.0f};
            mma16816(z, a2[0], w2f[0]);
            mma16816(z, a2[1], w2f[1]);

            za[mt][0] = sigm(z[0] + b2r0);
            za[mt][1] = sigm(z[1] + b2r1);
            za[mt][2] = sigm(z[2] + b2r0);
            za[mt][3] = sigm(z[3] + b2r1);
        }

        // ---- scatter batch b (att via shfl; reg indices compile-time) ----
        #pragma unroll
        for (int i = 0; i < 16; i++) {
            // e = 2i + half; bits 3/4 of e are lane-uniform (half only flips bit0)
            const int mtE  = i >> 3;            // e >> 4
            const int baseZ = (i & 4) ? 2 : 0;  // (e & 8) ? 2 : 0
            int srcl = 4 * ((2 * i) & 7) + 4 * half + hquad;  // 4*(e&7)+head/2
            float v0 = __shfl_sync(0xffffffffu, za[mtE][baseZ + 0], srcl);
            float v1 = __shfl_sync(0xffffffffu, za[mtE][baseZ + 1], srcl);
            float av = hsel ? v1 : v0;

            int e = 2 * i + half;
            int2 sd = eW[b * 32 + e];
            float4 sv = *(const float4*)(g_src_buf + (size_t)sd.x * FF + 4 * sub);
            red4(out + (size_t)sd.y * FF + 4 * sub,
                 av * sv.x, av * sv.y, av * sv.z, av * sv.w);
        }
        __syncwarp();   // gather(b+1) STS now visible; LDGs long since landed
    }
}

// ---------------------------------------------------------------------------
extern "C" void kernel_launch(void* const* d_in, const int* in_sizes, int n_in,
                              void* d_out, int out_size)
{
    const float* h      = (const float*)d_in[0];
    const float* W_src  = (const float*)d_in[1];
    const float* b_src  = (const float*)d_in[2];
    const float* W_dst  = (const float*)d_in[3];
    const float* b_dst  = (const float*)d_in[4];
    const float* Wa1_s  = (const float*)d_in[5];
    const float* ba1_s  = (const float*)d_in[6];
    const float* Wa2_s  = (const float*)d_in[7];
    const float* ba2_s  = (const float*)d_in[8];
    const float* Wa1_d  = (const float*)d_in[9];
    const float* ba1_d  = (const float*)d_in[10];
    const float* Wa2_d  = (const float*)d_in[11];
    const float* ba2_d  = (const float*)d_in[12];
    const void*  eidx   = (const void*)d_in[13];
    float* out = (float*)d_out;

    node_kernel<<<(NN + 127) / 128, 128>>>(
        h, W_src, b_src, W_dst, b_dst,
        Wa1_d, ba1_d, Wa2_d, ba2_d,
        (const unsigned int*)eidx, out);

    edge_kernel<<<EE / (4 * 5 * 32), 128>>>(
        eidx, Wa1_s, ba1_s, Wa2_s, ba2_s, out);
}

// round 17
// speedup vs baseline: 1.0923x; 1.0923x over previous
#include <cuda_runtime.h>
#include <cuda_bf16.h>

#define NN 100000
#define FF 64
#define HH 8
#define DD 8
#define EE 1200000
#define HID 32

// scratch (allocation-free rule: __device__ globals)
__device__ float g_src_buf[NN * FF];
__device__ float g_dst_buf[NN * FF];
__device__ int g_idx_is64;

__device__ __forceinline__ float leaky(float x) { return fmaxf(x, 0.2f * x); }
__device__ __forceinline__ float sigm(float x) { return 1.0f / (1.0f + __expf(-x)); }

__device__ __forceinline__ void red4(float* p, float x, float y, float z, float w) {
    asm volatile("red.global.add.v4.f32 [%0], {%1,%2,%3,%4};"
                 :: "l"(p), "f"(x), "f"(y), "f"(z), "f"(w) : "memory");
}

__device__ __forceinline__ unsigned pack_bf16(float lo, float hi) {
    __nv_bfloat162 t = __float22bfloat162_rn(make_float2(lo, hi));
    return *(unsigned*)&t;
}

// split x into bf16 hi + bf16 lo (residual)
__device__ __forceinline__ void split_pack(float a, float b, unsigned& hi, unsigned& lo) {
    __nv_bfloat16 ah = __float2bfloat16(a), bh = __float2bfloat16(b);
    float ar = a - __bfloat162float(ah);
    float br = b - __bfloat162float(bh);
    __nv_bfloat162 t; t.x = ah; t.y = bh;
    hi = *(unsigned*)&t;
    lo = pack_bf16(ar, br);
}

// D += A@B, m16n8k16, bf16 in / fp32 accum
__device__ __forceinline__ void mma16816(float* d, const unsigned* a, const unsigned* b) {
    asm volatile(
        "mma.sync.aligned.m16n8k16.row.col.f32.bf16.bf16.f32 "
        "{%0,%1,%2,%3}, {%4,%5,%6,%7}, {%8,%9}, {%0,%1,%2,%3};"
        : "+f"(d[0]), "+f"(d[1]), "+f"(d[2]), "+f"(d[3])
        : "r"(a[0]), "r"(a[1]), "r"(a[2]), "r"(a[3]), "r"(b[0]), "r"(b[1]));
}

#define LMW32 36               // staging row stride in uint32 (72 bf16), conflict-free
#define ATTS 10                // att row stride (node kernel only)

// ---------------------------------------------------------------------------
// Fused node kernel (unchanged): tensor-core GEMM (hi/lo split) + node att.
__global__ __launch_bounds__(128) void node_kernel(
    const float* __restrict__ h,
    const float* __restrict__ W_src, const float* __restrict__ b_src,
    const float* __restrict__ W_dst, const float* __restrict__ b_dst,
    const float* __restrict__ Wa1, const float* __restrict__ ba1,
    const float* __restrict__ Wa2, const float* __restrict__ ba2,
    const unsigned int* __restrict__ eidx_words,
    float* __restrict__ out)
{
    __shared__ unsigned AHI[128 * LMW32];
    __shared__ unsigned ALO[128 * LMW32];
    __shared__ float ATT[4][32 * ATTS];

    const int tid  = threadIdx.x;
    const int warp = tid >> 5;
    const int lane = tid & 31;
    const int c = lane & 3;
    const int r = lane >> 2;
    const int blockbase = blockIdx.x * 128;

    if (blockIdx.x == 0 && tid == 0) {
        int is64 = 1;
        for (int i = 0; i < 8; i++)
            if (eidx_words[2 * i + 1] != 0u) is64 = 0;
        g_idx_is64 = is64;
    }

    const int mat = warp >> 1;
    const int colbase = 32 * (warp & 1);
    const float* Wm = mat ? W_dst : W_src;
    const float* bm = mat ? b_dst : b_src;

    unsigned bhi[4][4][2], blo[4][4][2];
    #pragma unroll
    for (int ks = 0; ks < 4; ks++)
        #pragma unroll
        for (int nt = 0; nt < 4; nt++) {
            const float* base = Wm + (16 * ks + 2 * c) * FF + colbase + 8 * nt + r;
            split_pack(base[0],       base[FF],     bhi[ks][nt][0], blo[ks][nt][0]);
            split_pack(base[8 * FF],  base[9 * FF], bhi[ks][nt][1], blo[ks][nt][1]);
        }
    float gb0[4], gb1[4];
    #pragma unroll
    for (int nt = 0; nt < 4; nt++) {
        gb0[nt] = bm[colbase + 8 * nt + 2 * c];
        gb1[nt] = bm[colbase + 8 * nt + 2 * c + 1];
    }

    unsigned w1f[4][4][2];
    #pragma unroll
    for (int ks = 0; ks < 4; ks++)
        #pragma unroll
        for (int nt = 0; nt < 4; nt++) {
            const float* base = Wa1 + (16 * ks + 2 * c) * HID + 8 * nt + r;
            w1f[ks][nt][0] = pack_bf16(base[0],        base[HID]);
            w1f[ks][nt][1] = pack_bf16(base[8 * HID],  base[9 * HID]);
        }
    unsigned w2f[2][2];
    #pragma unroll
    for (int ks = 0; ks < 2; ks++) {
        const float* base = Wa2 + (16 * ks + 2 * c) * HH + r;
        w2f[ks][0] = pack_bf16(base[0],      base[HH]);
        w2f[ks][1] = pack_bf16(base[8 * HH], base[9 * HH]);
    }
    float bb0[4], bb1[4];
    #pragma unroll
    for (int nt = 0; nt < 4; nt++) {
        bb0[nt] = ba1[8 * nt + 2 * c];
        bb1[nt] = ba1[8 * nt + 2 * c + 1];
    }
    const float b2r0 = ba2[2 * c], b2r1 = ba2[2 * c + 1];

    #pragma unroll
    for (int e = 0; e < 32; e++) {
        int row = blockbase + 32 * warp + e;
        float2 v = (row < NN) ? *(const float2*)(h + (size_t)row * FF + 2 * lane)
                              : make_float2(0.0f, 0.0f);
        unsigned hv, lv;
        split_pack(v.x, v.y, hv, lv);
        AHI[(32 * warp + e) * LMW32 + lane] = hv;
        ALO[(32 * warp + e) * LMW32 + lane] = lv;
    }
    __syncthreads();

    float* gout = mat ? g_dst_buf : g_src_buf;
    #pragma unroll
    for (int mt = 0; mt < 8; mt++) {
        float acc[4][4];
        #pragma unroll
        for (int nt = 0; nt < 4; nt++)
            acc[nt][0] = acc[nt][1] = acc[nt][2] = acc[nt][3] = 0.0f;

        #pragma unroll
        for (int ks = 0; ks < 4; ks++) {
            int base = (mt * 16 + r) * LMW32 + 8 * ks + c;
            unsigned ah[4], al[4];
            ah[0] = AHI[base];                 al[0] = ALO[base];
            ah[1] = AHI[base + 8 * LMW32];     al[1] = ALO[base + 8 * LMW32];
            ah[2] = AHI[base + 4];             al[2] = ALO[base + 4];
            ah[3] = AHI[base + 8 * LMW32 + 4]; al[3] = ALO[base + 8 * LMW32 + 4];
            #pragma unroll
            for (int nt = 0; nt < 4; nt++) {
                mma16816(acc[nt], ah, blo[ks][nt]);
                mma16816(acc[nt], al, bhi[ks][nt]);
                mma16816(acc[nt], ah, bhi[ks][nt]);
            }
        }

        int row0 = blockbase + 16 * mt + r;
        int row8 = row0 + 8;
        #pragma unroll
        for (int nt = 0; nt < 4; nt++) {
            int col = colbase + 8 * nt + 2 * c;
            if (row0 < NN)
                *(float2*)(gout + (size_t)row0 * FF + col) =
                    make_float2(acc[nt][0] + gb0[nt], acc[nt][1] + gb1[nt]);
            if (row8 < NN)
                *(float2*)(gout + (size_t)row8 * FF + col) =
                    make_float2(acc[nt][2] + gb0[nt], acc[nt][3] + gb1[nt]);
        }
    }
    __syncthreads();

    const int nbase = blockbase + 32 * warp;
    if (nbase >= NN) return;

    unsigned* lmW = &AHI[(32 * warp) * LMW32];
    float* attW = &ATT[warp][0];
    const int myh = lane >> 2;

    #pragma unroll
    for (int e = 0; e < 32; e++) {
        float2 dv = *(const float2*)(g_dst_buf + (size_t)(nbase + e) * FF + 2 * lane);
        lmW[e * LMW32 + lane] = pack_bf16(leaky(dv.x), leaky(dv.y));
    }
    __syncwarp();

    #pragma unroll
    for (int mt = 0; mt < 2; mt++) {
        float acc[4][4];
        #pragma unroll
        for (int nt = 0; nt < 4; nt++)
            acc[nt][0] = acc[nt][1] = acc[nt][2] = acc[nt][3] = 0.0f;

        #pragma unroll
        for (int ks = 0; ks < 4; ks++) {
            unsigned a[4];
            int base = (mt * 16 + r) * LMW32 + 8 * ks + c;
            a[0] = lmW[base];
            a[1] = lmW[base + 8 * LMW32];
            a[2] = lmW[base + 4];
            a[3] = lmW[base + 8 * LMW32 + 4];
            #pragma unroll
            for (int nt = 0; nt < 4; nt++)
                mma16816(acc[nt], a, w1f[ks][nt]);
        }

        unsigned a2[2][4];
        #pragma unroll
        for (int nt = 0; nt < 4; nt++) {
            float v0 = leaky(acc[nt][0] + bb0[nt]);
            float v1 = leaky(acc[nt][1] + bb1[nt]);
            float v2 = leaky(acc[nt][2] + bb0[nt]);
            float v3 = leaky(acc[nt][3] + bb1[nt]);
            a2[nt >> 1][(nt & 1) * 2 + 0] = pack_bf16(v0, v1);
            a2[nt >> 1][(nt & 1) * 2 + 1] = pack_bf16(v2, v3);
        }

        float z[4] = {0.0f, 0.0f, 0.0f, 0.0f};
        mma16816(z, a2[0], w2f[0]);
        mma16816(z, a2[1], w2f[1]);

        *(float2*)&attW[(mt * 16 + r) * ATTS + 2 * c] =
            make_float2(sigm(z[0] + b2r0), sigm(z[1] + b2r1));
        *(float2*)&attW[(mt * 16 + r + 8) * ATTS + 2 * c] =
            make_float2(sigm(z[2] + b2r0), sigm(z[3] + b2r1));
    }
    __syncwarp();

    #pragma unroll
    for (int e = 0; e < 32; e++) {
        float av = attW[e * ATTS + myh];
        float2 dv = *(const float2*)(g_dst_buf + (size_t)(nbase + e) * FF + 2 * lane);
        *(float2*)(out + (size_t)(nbase + e) * FF + 2 * lane) =
            make_float2(av * dv.x, av * dv.y);
    }
}

// ---------------------------------------------------------------------------
// Edge kernel v10 = v8 (reg-att + shfl exchange, gather-before-MMA, one
// syncwarp after scatter) with ALL 5 batches' indices preloaded into
// REGISTERS in the prologue — removes the per-batch index-LDG round trip
// from the gather critical path. Main loop fully unrolled so the index
// arrays stay in registers.
__global__ __launch_bounds__(128, 4) void edge_kernel(
    const void* __restrict__ edge_index,
    const float* __restrict__ Wa1, const float* __restrict__ ba1,
    const float* __restrict__ Wa2, const float* __restrict__ ba2,
    float* __restrict__ out)
{
    __shared__ unsigned LM[4][2][32 * LMW32];   // double-buffered per warp

    const int tid  = threadIdx.x;
    const int warp = tid >> 5;
    const int lane = tid & 31;
    const int c = lane & 3;
    const int r = lane >> 2;
    const int half = lane >> 4;      // which edge of the pair
    const int sub  = lane & 15;      // 16B chunk within row
    const int hsel = (sub >> 1) & 1; // which of the source lane's 2 heads
    const int hquad = sub >> 2;      // source-lane column (head/2)

    unsigned w1f[4][4][2];
    #pragma unroll
    for (int ks = 0; ks < 4; ks++)
        #pragma unroll
        for (int nt = 0; nt < 4; nt++) {
            const float* base = Wa1 + (16 * ks + 2 * c) * HID + 8 * nt + r;
            w1f[ks][nt][0] = pack_bf16(base[0],        base[HID]);
            w1f[ks][nt][1] = pack_bf16(base[8 * HID],  base[9 * HID]);
        }
    unsigned w2f[2][2];
    #pragma unroll
    for (int ks = 0; ks < 2; ks++) {
        const float* base = Wa2 + (16 * ks + 2 * c) * HH + r;
        w2f[ks][0] = pack_bf16(base[0],      base[HH]);
        w2f[ks][1] = pack_bf16(base[8 * HH], base[9 * HH]);
    }
    float bb0[4], bb1[4];
    #pragma unroll
    for (int nt = 0; nt < 4; nt++) {
        bb0[nt] = ba1[8 * nt + 2 * c];
        bb1[nt] = ba1[8 * nt + 2 * c + 1];
    }
    const float b2r0 = ba2[2 * c], b2r1 = ba2[2 * c + 1];

    const int wbase = (blockIdx.x * 4 + warp) * 5;

    // ---- preload ALL 5 batches' indices into registers (parallel LDGs) ----
    int srcI[5], dstI[5];
    {
        const int is64 = g_idx_is64;
        if (is64) {
            const long long* ei = (const long long*)edge_index;
            #pragma unroll
            for (int b = 0; b < 5; b++) {
                srcI[b] = (int)ei[(wbase + b) * 32 + lane];
                dstI[b] = (int)ei[EE + (wbase + b) * 32 + lane];
            }
        } else {
            const int* ei = (const int*)edge_index;
            #pragma unroll
            for (int b = 0; b < 5; b++) {
                srcI[b] = ei[(wbase + b) * 32 + lane];
                dstI[b] = ei[EE + (wbase + b) * 32 + lane];
            }
        }
    }

    // gather a full batch (fp32 rows) into LM buffer
    auto gather = [&](int srcR, int dstR, unsigned* lmB) {
        #pragma unroll
        for (int i = 0; i < 16; i++) {
            int e = 2 * i + half;
            int s = __shfl_sync(0xffffffffu, srcR, e);
            int d = __shfl_sync(0xffffffffu, dstR, e);
            float4 sv = *(const float4*)(g_src_buf + (size_t)s * FF + 4 * sub);
            float4 dv = *(const float4*)(g_dst_buf + (size_t)d * FF + 4 * sub);
            *(uint2*)&lmB[e * LMW32 + 2 * sub] = make_uint2(
                pack_bf16(leaky(sv.x + dv.x), leaky(sv.y + dv.y)),
                pack_bf16(leaky(sv.z + dv.z), leaky(sv.w + dv.w)));
        }
    };

    gather(srcI[0], dstI[0], &LM[warp][0][0]);
    __syncwarp();

    #pragma unroll
    for (int b = 0; b < 5; b++) {
        // issue next batch's gather (other buffer, no sync — hides under MMA)
        if (b < 4) gather(srcI[b + 1], dstI[b + 1], &LM[warp][(b + 1) & 1][0]);

        // ---- MMA MLP on batch b (att kept in registers, sigm applied) ----
        unsigned* lmW = &LM[warp][b & 1][0];
        float za[2][4];
        #pragma unroll
        for (int mt = 0; mt < 2; mt++) {
            float acc[4][4];
            #pragma unroll
            for (int nt = 0; nt < 4; nt++)
                acc[nt][0] = acc[nt][1] = acc[nt][2] = acc[nt][3] = 0.0f;

            #pragma unroll
            for (int ks = 0; ks < 4; ks++) {
                unsigned a[4];
                int base = (mt * 16 + r) * LMW32 + 8 * ks + c;
                a[0] = lmW[base];
                a[1] = lmW[base + 8 * LMW32];
                a[2] = lmW[base + 4];
                a[3] = lmW[base + 8 * LMW32 + 4];
                #pragma unroll
                for (int nt = 0; nt < 4; nt++)
                    mma16816(acc[nt], a, w1f[ks][nt]);
            }

            unsigned a2[2][4];
            #pragma unroll
            for (int nt = 0; nt < 4; nt++) {
                float v0 = leaky(acc[nt][0] + bb0[nt]);
                float v1 = leaky(acc[nt][1] + bb1[nt]);
                float v2 = leaky(acc[nt][2] + bb0[nt]);
                float v3 = leaky(acc[nt][3] + bb1[nt]);
                a2[nt >> 1][(nt & 1) * 2 + 0] = pack_bf16(v0, v1);
                a2[nt >> 1][(nt & 1) * 2 + 1] = pack_bf16(v2, v3);
            }

            float z[4] = {0.0f, 0.0f, 0.0f, 0.0f};
            mma16816(z, a2[0], w2f[0]);
            mma16816(z, a2[1], w2f[1]);

            // za[mt]: edge (mt*16+r) heads {2c,2c+1} = z0,z1;
            //         edge (mt*16+r+8)            = z2,z3
            za[mt][0] = sigm(z[0] + b2r0);
            za[mt][1] = sigm(z[1] + b2r1);
            za[mt][2] = sigm(z[2] + b2r0);
            za[mt][3] = sigm(z[3] + b2r1);
        }

        // ---- scatter batch b (att via shfl; reg indices compile-time) ----
        #pragma unroll
        for (int i = 0; i < 16; i++) {
            // e = 2i + half; bits 3/4 of e are lane-uniform (half only flips bit0)
            const int mtE  = i >> 3;            // e >> 4
            const int baseZ = (i & 4) ? 2 : 0;  // (e & 8) ? 2 : 0
            int srcl = 4 * ((2 * i) & 7) + 4 * half + hquad;  // 4*(e&7)+head/2
            float v0 = __shfl_sync(0xffffffffu, za[mtE][baseZ + 0], srcl);
            float v1 = __shfl_sync(0xffffffffu, za[mtE][baseZ + 1], srcl);
            float av = hsel ? v1 : v0;

            int e = 2 * i + half;
            int s = __shfl_sync(0xffffffffu, srcI[b], e);
            int d = __shfl_sync(0xffffffffu, dstI[b], e);
            float4 sv = *(const float4*)(g_src_buf + (size_t)s * FF + 4 * sub);
            red4(out + (size_t)d * FF + 4 * sub,
                 av * sv.x, av * sv.y, av * sv.z, av * sv.w);
        }
        __syncwarp();   // gather(b+1) STS now visible; LDGs long since landed
    }
}

// ---------------------------------------------------------------------------
extern "C" void kernel_launch(void* const* d_in, const int* in_sizes, int n_in,
                              void* d_out, int out_size)
{
    const float* h      = (const float*)d_in[0];
    const float* W_src  = (const float*)d_in[1];
    const float* b_src  = (const float*)d_in[2];
    const float* W_dst  = (const float*)d_in[3];
    const float* b_dst  = (const float*)d_in[4];
    const float* Wa1_s  = (const float*)d_in[5];
    const float* ba1_s  = (const float*)d_in[6];
    const float* Wa2_s  = (const float*)d_in[7];
    const float* ba2_s  = (const float*)d_in[8];
    const float* Wa1_d  = (const float*)d_in[9];
    const float* ba1_d  = (const float*)d_in[10];
    const float* Wa2_d  = (const float*)d_in[11];
    const float* ba2_d  = (const float*)d_in[12];
    const void*  eidx   = (const void*)d_in[13];
    float* out = (float*)d_out;

    node_kernel<<<(NN + 127) / 128, 128>>>(
        h, W_src, b_src, W_dst, b_dst,
        Wa1_d, ba1_d, Wa2_d, ba2_d,
        (const unsigned int*)eidx, out);

    edge_kernel<<<EE / (4 * 5 * 32), 128>>>(
        eidx, Wa1_s, ba1_s, Wa2_s, ba2_s, out);
}